// round 11
// baseline (speedup 1.0000x reference)
#include <cuda_runtime.h>
#include <cstdint>

#define T_LEN 6000
#define BATCH 64
#define HID   128
#define PROJ  32
#define G4    512

typedef unsigned long long u64;

// ---------------- scratch ----------------
__device__ float g_xi [(size_t)T_LEN * BATCH * G4];    // xi0 (X -> C0)
__device__ float g_xi1[(size_t)T_LEN * BATCH * G4];    // xi1 (G -> C1)
__device__ float g_h0 [(size_t)T_LEN * BATCH * PROJ];  // h0  (C0 -> G)
__device__ int   g_wmx[BATCH];                         // xi0 watermark
__device__ int   g_wm0[BATCH];                         // h0 watermark
__device__ int   g_wm1[BATCH];                         // xi1 watermark

// ---------------- f32x2 helpers ----------------
__device__ __forceinline__ u64 pk(float lo, float hi) {
    u64 r;
    asm("mov.b64 %0, {%1, %2};" : "=l"(r) : "f"(lo), "f"(hi));
    return r;
}
__device__ __forceinline__ void upk(u64 a, float& lo, float& hi) {
    asm("mov.b64 {%0, %1}, %2;" : "=f"(lo), "=f"(hi) : "l"(a));
}
__device__ __forceinline__ void fma2(u64& d, u64 a, u64 b) {
    asm("fma.rn.f32x2 %0, %1, %2, %3;" : "=l"(d) : "l"(a), "l"(b), "l"(d));
}
__device__ __forceinline__ u64 add2(u64 a, u64 b) {
    u64 r;
    asm("add.rn.f32x2 %0, %1, %2;" : "=l"(r) : "l"(a), "l"(b));
    return r;
}
__device__ __forceinline__ float hsum(u64 a) {
    float lo, hi; upk(a, lo, hi); return lo + hi;
}

// ---------------- activations ----------------
__device__ __forceinline__ float tanh_hw(float x) {
    float r; asm("tanh.approx.f32 %0, %1;" : "=f"(r) : "f"(x)); return r;
}
__device__ __forceinline__ float sigm(float x) {
    return fmaf(tanh_hw(x * 0.5f), 0.5f, 0.5f);
}
__device__ __forceinline__ float ex2_(float x) {
    float r; asm("ex2.approx.f32 %0, %1;" : "=f"(r) : "f"(x)); return r;
}
__device__ __forceinline__ float rcp_(float x) {
    float r; asm("rcp.approx.f32 %0, %1;" : "=f"(r) : "f"(x)); return r;
}
__device__ __forceinline__ float sigm_acc(float x) {
    return rcp_(1.f + ex2_(-x * 1.4426950408889634f));
}

// ---------------- flag ops ----------------
__device__ __forceinline__ void wm_store(int* p, int v) {
    asm volatile("st.release.gpu.global.s32 [%0], %1;" :: "l"(p), "r"(v) : "memory");
}
__device__ __forceinline__ int wm_load(const int* p) {
    int v;
    asm volatile("ld.acquire.gpu.global.s32 %0, [%1];" : "=r"(v) : "l"(p) : "memory");
    return v;
}

__global__ void init_wm() {
    if (threadIdx.x < BATCH) {
        g_wmx[threadIdx.x] = 0;
        g_wm0[threadIdx.x] = 0;
        g_wm1[threadIdx.x] = 0;
    }
}

// ---------------- LSTM cell body (C0 / C1), R7 cadence ----------------
template<bool EMIT_H0, bool EMIT_OUT>
__device__ __forceinline__ void cell_phase(
    int b, const float* __restrict__ xsrc, const int* __restrict__ wm_in,
    int* __restrict__ wm_out, const float* __restrict__ Whh,
    const float* __restrict__ Whr, const float* __restrict__ W2,
    const float* __restrict__ b2, float* __restrict__ h0out,
    float* __restrict__ out)
{
    const int u = threadIdx.x;
    const int w = u >> 5, l = u & 31;

    __shared__ __align__(16) float ots[128];
    __shared__ __align__(16) float hp[2][4][32];
    __shared__ __align__(16) float hbw[4][32];

    u64 whh[4][16];
#pragma unroll
    for (int q = 0; q < 4; q++) {
        const u64* p = reinterpret_cast<const u64*>(Whh + (q * HID + u) * PROJ);
#pragma unroll
        for (int j = 0; j < 16; j++) whh[q][j] = p[j];
    }
    u64 whr[16];
    {
        const u64* wr = reinterpret_cast<const u64*>(Whr + l * HID + w * 32);
#pragma unroll
        for (int j = 0; j < 16; j++) whr[j] = wr[j];
    }
    float w2v = 0.f, b2v = 0.f;
    if (EMIT_OUT) { w2v = W2[l]; b2v = b2[0]; }

    hbw[w][l] = 0.f;
    float c = 0.f;
    __syncthreads();

    const size_t strideT = (size_t)BATCH * G4;
    const float* xp = xsrc + (size_t)b * G4 + u;

    int wmv = 0;
    if (wm_in) { while ((wmv = wm_load(wm_in)) < 8) __nanosleep(200); }

    float buf[4][4];
#pragma unroll
    for (int k = 0; k < 4; k++) {
        const float* xn = xp + (size_t)k * strideT;
#pragma unroll
        for (int q = 0; q < 4; q++) buf[k][q] = xn[q * HID];
    }

    for (int t4 = 0; t4 < T_LEN / 4; t4++) {
        if (wm_in && t4) {
            int need = t4 * 4 + 8; if (need > T_LEN) need = T_LEN;
            while (wmv < need) { wmv = wm_load(wm_in); if (wmv < need) __nanosleep(100); }
        }
#pragma unroll
        for (int k = 0; k < 4; k++) {
            const int t = t4 * 4 + k;
            float g0 = buf[k][0], g1 = buf[k][1], g2 = buf[k][2], g3 = buf[k][3];
            if (t + 4 < T_LEN) {
                const float* xn = xp + (size_t)(t + 4) * strideT;
#pragma unroll
                for (int q = 0; q < 4; q++) buf[k][q] = xn[q * HID];
            }
            const u64* h2 = reinterpret_cast<const u64*>(hbw[w]);
            u64 aA0 = pk(0.f,0.f), aA1 = aA0, aA2 = aA0, aA3 = aA0;
            u64 aB0 = aA0, aB1 = aA0, aB2 = aA0, aB3 = aA0;
#pragma unroll
            for (int j = 0; j < 8; j++) {
                u64 hv = h2[j];
                fma2(aA0, whh[0][j], hv); fma2(aA1, whh[1][j], hv);
                fma2(aA2, whh[2][j], hv); fma2(aA3, whh[3][j], hv);
            }
#pragma unroll
            for (int j = 8; j < 16; j++) {
                u64 hv = h2[j];
                fma2(aB0, whh[0][j], hv); fma2(aB1, whh[1][j], hv);
                fma2(aB2, whh[2][j], hv); fma2(aB3, whh[3][j], hv);
            }
            g0 += hsum(add2(aA0, aB0));
            g1 += hsum(add2(aA1, aB1));
            g2 += hsum(add2(aA2, aB2));
            g3 += hsum(add2(aA3, aB3));

            float iv = sigm(g0), fv = sigm(g1);
            float gv = tanh_hw(g2), ov = sigm(g3);
            c = fmaf(fv, c, iv * gv);
            float ot = ov * tanh_hw(c);

            ots[u] = ot;
            __syncwarp();
            const u64* o2 = reinterpret_cast<const u64*>(ots) + w * 16;
            u64 pA = pk(0.f,0.f), pB = pA;
#pragma unroll
            for (int j = 0; j < 8; j++)  fma2(pA, whr[j], o2[j]);
#pragma unroll
            for (int j = 8; j < 16; j++) fma2(pB, whr[j], o2[j]);
            hp[k & 1][w][l] = hsum(add2(pA, pB));
            __syncthreads();
            const float (*hpv)[32] = hp[k & 1];
            float hv = (hpv[0][l] + hpv[1][l]) + (hpv[2][l] + hpv[3][l]);
            hbw[w][l] = hv;
            if (EMIT_H0) {
                if (w == 0) h0out[((size_t)t * BATCH + b) * PROJ + l] = hv;
            }
            if (EMIT_OUT) {
                if (w == 0) {
                    float val = fmaxf(hv, 0.f) * w2v;
#pragma unroll
                    for (int off = 16; off; off >>= 1)
                        val += __shfl_down_sync(0xffffffffu, val, off);
                    if (l == 0) {
                        float z = fmaxf(val + b2v, 0.f);
                        out[(size_t)b * T_LEN + t] = sigm_acc(z);
                    }
                }
            }
            __syncwarp();
        }
        if (EMIT_H0) {
            if (w == 0) {
                __threadfence();
                __syncwarp();
                if (l == 0) wm_store(wm_out, t4 * 4 + 4);
            }
        }
    }
}

// ---------------- X-role helpers (xi0 producer, 128 threads) ----------------
// load x window (8 timesteps at t0): thread covers idx = u, u+128 (<160)
__device__ __forceinline__ void x_loadx(const float* __restrict__ x, int b, int t0,
                                        float4& r0, float4& r1)
{
    const int u = threadIdx.x;
    {
        int f = u >> 1, half = u & 1;
        r0 = *reinterpret_cast<const float4*>(
            x + (size_t)(b * 80 + f) * T_LEN + t0 + half * 4);
    }
    if (u < 32) {
        int idx = 128 + u, f = idx >> 1, half = idx & 1;
        r1 = *reinterpret_cast<const float4*>(
            x + (size_t)(b * 80 + f) * T_LEN + t0 + half * 4);
    }
}
__device__ __forceinline__ void x_stagex(u64 (*xwin)[4], float4 r0, float4 r1)
{
    const int u = threadIdx.x;
    {
        int f = u >> 1, half = u & 1;
        xwin[f][half * 2]     = pk(r0.x, r0.y);
        xwin[f][half * 2 + 1] = pk(r0.z, r0.w);
    }
    if (u < 32) {
        int idx = 128 + u, f = idx >> 1, half = idx & 1;
        xwin[f][half * 2]     = pk(r1.x, r1.y);
        xwin[f][half * 2 + 1] = pk(r1.z, r1.w);
    }
}
// produce one 8-step xi0 tile from staged xwin
__device__ __forceinline__ void x_produce(const u64 (*xwin)[4],
                                          const float* __restrict__ Wih0,
                                          const float* __restrict__ bias0q,
                                          int b, int tile)
{
    const int u  = threadIdx.x;
    const int t0 = tile * 8;
    u64 acc[4][4];
#pragma unroll
    for (int q = 0; q < 4; q++)
#pragma unroll
        for (int p = 0; p < 4; p++) acc[q][p] = pk(bias0q[q], bias0q[q]);
#pragma unroll 4
    for (int f4 = 0; f4 < 20; f4++) {
        u64 xv[4][4];
#pragma unroll
        for (int ff = 0; ff < 4; ff++) {
            uint32_t sa = (uint32_t)__cvta_generic_to_shared(&xwin[f4 * 4 + ff][0]);
            asm("ld.shared.v2.u64 {%0, %1}, [%2];"    : "=l"(xv[ff][0]), "=l"(xv[ff][1]) : "r"(sa));
            asm("ld.shared.v2.u64 {%0, %1}, [%2+16];" : "=l"(xv[ff][2]), "=l"(xv[ff][3]) : "r"(sa));
        }
#pragma unroll
        for (int q = 0; q < 4; q++) {
            float4 wv = *reinterpret_cast<const float4*>(Wih0 + (q * HID + u) * 80 + f4 * 4);
            u64 w0 = pk(wv.x, wv.x), w1 = pk(wv.y, wv.y);
            u64 w2 = pk(wv.z, wv.z), w3 = pk(wv.w, wv.w);
#pragma unroll
            for (int p = 0; p < 4; p++) {
                fma2(acc[q][p], w0, xv[0][p]); fma2(acc[q][p], w1, xv[1][p]);
                fma2(acc[q][p], w2, xv[2][p]); fma2(acc[q][p], w3, xv[3][p]);
            }
        }
    }
    const size_t st = (size_t)BATCH * G4;
    float* xo = g_xi + ((size_t)t0 * BATCH + b) * G4 + u;
#pragma unroll
    for (int q = 0; q < 4; q++)
#pragma unroll
        for (int p = 0; p < 4; p++) {
            float lo, hi; upk(acc[q][p], lo, hi);
            xo[(size_t)(2 * p)     * st + q * HID] = lo;
            xo[(size_t)(2 * p + 1) * st + q * HID] = hi;
        }
}

// ---------------- 4-stage pipelined scan over 256 blocks ----------------
// roles: 0-63 C0, 64-127 G(xi1), 128-191 C1, 192-255 X(xi0 producer)
__global__ void __launch_bounds__(128, 1) scan4(
    const float* __restrict__ x,
    const float* __restrict__ Wih0,
    const float* __restrict__ bih0, const float* __restrict__ bhh0,
    const float* __restrict__ Whh0, const float* __restrict__ Whr0,
    const float* __restrict__ Wih1,
    const float* __restrict__ bih1, const float* __restrict__ bhh1,
    const float* __restrict__ Whh1, const float* __restrict__ Whr1,
    const float* __restrict__ W2,   const float* __restrict__ b2,
    float* __restrict__ out)
{
    const int role = blockIdx.x >> 6;      // 0: C0, 1: G, 2: C1, 3: X
    const int b    = blockIdx.x & 63;
    const int u    = threadIdx.x;

    if (role == 0) {
        cell_phase<true, false>(b, g_xi, g_wmx + b, g_wm0 + b,
                                Whh0, Whr0, nullptr, nullptr, g_h0, nullptr);
    } else if (role == 1) {
        // ---- G: xi1 gemv, 8-step windows (R7-proven) ----
        __shared__ __align__(16) float h0win[8][32];

        u64 wih[4][16];
        float biasq[4];
#pragma unroll
        for (int q = 0; q < 4; q++) {
            const u64* p = reinterpret_cast<const u64*>(Wih1 + (q * HID + u) * PROJ);
#pragma unroll
            for (int j = 0; j < 16; j++) wih[q][j] = p[j];
            biasq[q] = bih1[q * HID + u] + bhh1[q * HID + u];
        }

        int wmv = 0;
        for (int w8 = 0; w8 < T_LEN / 8; w8++) {
            const int need = w8 * 8 + 8;
            while (wmv < need) { wmv = wm_load(&g_wm0[b]); if (wmv < need) __nanosleep(100); }
#pragma unroll
            for (int r = 0; r < 2; r++) {
                int idx = u + r * 128;
                int tt = idx >> 5, jj = idx & 31;
                h0win[tt][jj] =
                    g_h0[((size_t)(w8 * 8 + tt) * BATCH + b) * PROJ + jj];
            }
            __syncthreads();
#pragma unroll 2
            for (int k = 0; k < 8; k++) {
                const u64* h2 = reinterpret_cast<const u64*>(h0win[k]);
                u64 aA0 = pk(0.f,0.f), aA1 = aA0, aA2 = aA0, aA3 = aA0;
                u64 aB0 = aA0, aB1 = aA0, aB2 = aA0, aB3 = aA0;
#pragma unroll
                for (int j = 0; j < 8; j++) {
                    u64 hv = h2[j];
                    fma2(aA0, wih[0][j], hv); fma2(aA1, wih[1][j], hv);
                    fma2(aA2, wih[2][j], hv); fma2(aA3, wih[3][j], hv);
                }
#pragma unroll
                for (int j = 8; j < 16; j++) {
                    u64 hv = h2[j];
                    fma2(aB0, wih[0][j], hv); fma2(aB1, wih[1][j], hv);
                    fma2(aB2, wih[2][j], hv); fma2(aB3, wih[3][j], hv);
                }
                float* xo = g_xi1 + ((size_t)(w8 * 8 + k) * BATCH + b) * G4;
                xo[u]           = biasq[0] + hsum(add2(aA0, aB0));
                xo[HID + u]     = biasq[1] + hsum(add2(aA1, aB1));
                xo[2*HID + u]   = biasq[2] + hsum(add2(aA2, aB2));
                xo[3*HID + u]   = biasq[3] + hsum(add2(aA3, aB3));
            }
            __threadfence();
            __syncthreads();
            if (u == 0) wm_store(&g_wm1[b], w8 * 8 + 8);
        }
    } else if (role == 2) {
        cell_phase<false, true>(b, g_xi1, g_wm1 + b, nullptr,
                                Whh1, Whr1, W2, b2, nullptr, out);
    } else {
        // ---- X: xi0 producer, 8-step tiles in t-order ----
        __shared__ __align__(16) u64 xwin[2][80][4];

        float bias0q[4];
#pragma unroll
        for (int q = 0; q < 4; q++)
            bias0q[q] = bih0[q * HID + u] + bhh0[q * HID + u];

        float4 r0, r1;
        x_loadx(x, b, 0, r0, r1);

        for (int tile = 0; tile < T_LEN / 8; tile++) {
            x_stagex(xwin[tile & 1], r0, r1);
            __syncthreads();
            if (tile + 1 < T_LEN / 8) x_loadx(x, b, (tile + 1) * 8, r0, r1);
            x_produce(xwin[tile & 1], Wih0, bias0q, b, tile);
            __threadfence();
            __syncthreads();
            if (u == 0) wm_store(&g_wmx[b], tile * 8 + 8);
        }
    }
}

// ---------------- launch ----------------
extern "C" void kernel_launch(void* const* d_in, const int* in_sizes, int n_in,
                              void* d_out, int out_size)
{
    const float* x    = (const float*)d_in[0];
    const float* Wih0 = (const float*)d_in[1];
    const float* Whh0 = (const float*)d_in[2];
    const float* bih0 = (const float*)d_in[3];
    const float* bhh0 = (const float*)d_in[4];
    const float* Whr0 = (const float*)d_in[5];
    const float* Wih1 = (const float*)d_in[6];
    const float* Whh1 = (const float*)d_in[7];
    const float* bih1 = (const float*)d_in[8];
    const float* bhh1 = (const float*)d_in[9];
    const float* Whr1 = (const float*)d_in[10];
    const float* W2   = (const float*)d_in[11];
    const float* b2   = (const float*)d_in[12];
    float* out = (float*)d_out;

    init_wm<<<1, 64>>>();
    scan4<<<256, 128>>>(x, Wih0, bih0, bhh0, Whh0, Whr0,
                        Wih1, bih1, bhh1, Whh1, Whr1,
                        W2, b2, out);
}